// round 8
// baseline (speedup 1.0000x reference)
#include <cuda_runtime.h>
#include <cuda_fp16.h>
#include <cstdint>

// out[b, c, i] = in[b, c, parent_idx[i]]
// B*C = 64, N_IN = 1048576, N_OUT = 2097152, fp32.
//
// Pipeline:
//  1) transpose+convert in[64][1M] fp32 -> g_tin_h[1M][64] fp16 (128 MB).
//     One gathered row = 128B = exactly one cache line.
//  2) gather: 256 output indices per block, 4 independent random 128B row
//     loads in flight per thread (MLP=4), smem transpose, coalesced fp32
//     streaming stores.
// fp16 round-trip rel err ~2e-4 (norm), under the 1e-3 threshold.

#define N_IN_C   1048576
#define N_OUT_C  2097152
#define BC_C     64

// 128 MB scratch: transposed fp16 input, tin[n][bc]
__device__ __align__(256) __half g_tin_h[(size_t)N_IN_C * BC_C];

__device__ __forceinline__ void st_evict_last_32B(void* p, const uint64_t w[4])
{
    asm volatile("st.global.L2::evict_last.v4.b64 [%0], {%1,%2,%3,%4};"
                 :: "l"(p), "l"(w[0]), "l"(w[1]), "l"(w[2]), "l"(w[3])
                 : "memory");
}

__device__ __forceinline__ void ld_nc_32B(const void* p, uint64_t w[4])
{
    asm volatile("ld.global.nc.v4.b64 {%0,%1,%2,%3}, [%4];"
                 : "=l"(w[0]), "=l"(w[1]), "=l"(w[2]), "=l"(w[3]) : "l"(p));
}

// ---------------------------------------------------------------------------
// Kernel A: transpose+convert in[64][1M] fp32 -> g_tin_h[1M][64] fp16.
// Block: 64 bc x 64 n tile, 256 threads.
// ---------------------------------------------------------------------------
__global__ __launch_bounds__(256)
void transpose_h_kernel(const float* __restrict__ in)
{
    __shared__ float t[64][65];            // [n-within-tile][bc]
    const int n0  = blockIdx.x * 64;
    const int tid = threadIdx.x;

#pragma unroll
    for (int it = 0; it < 4; ++it) {
        int fid = it * 256 + tid;
        int bc  = fid >> 4;                // 0..63
        int jc  = fid & 15;                // float4 slot
        float4 v = __ldg(reinterpret_cast<const float4*>(
                             in + (size_t)bc * N_IN_C + n0) + jc);
        t[jc * 4 + 0][bc] = v.x;
        t[jc * 4 + 1][bc] = v.y;
        t[jc * 4 + 2][bc] = v.z;
        t[jc * 4 + 3][bc] = v.w;
    }
    __syncthreads();

    // Write: each n-row = 64 halfs = 128B; thread writes one 32B chunk.
    {
        int j = tid >> 2;                  // n within tile 0..63
        int q = tid & 3;                   // 32B chunk over bc
        uint64_t w[4];
#pragma unroll
        for (int k = 0; k < 4; ++k) {
            __half2 h0 = __float22half2_rn(
                make_float2(t[j][q * 16 + k * 4 + 0], t[j][q * 16 + k * 4 + 1]));
            __half2 h1 = __float22half2_rn(
                make_float2(t[j][q * 16 + k * 4 + 2], t[j][q * 16 + k * 4 + 3]));
            uint32_t a = *reinterpret_cast<uint32_t*>(&h0);
            uint32_t b = *reinterpret_cast<uint32_t*>(&h1);
            w[k] = (uint64_t)a | ((uint64_t)b << 32);
        }
        st_evict_last_32B(g_tin_h + (size_t)(n0 + j) * BC_C + q * 16, w);
    }
}

// ---------------------------------------------------------------------------
// Kernel B: gather. Block = 256 threads, 256 output indices, all 64 bc.
//  load : 4 threads per index read the 128B row as 32B v4.b64 chunks;
//         4 independent rows in flight per thread (MLP=4).
//         smem scatter pitch 261: bank = (8c + 10k + 5s + r) mod 32,
//         conflict-free (8c + r covers 0..31 within a warp).
//  write: 16 iters; thread writes float2 of one bc-pair, lanes cover 128
//         consecutive r-pairs -> fully coalesced streaming stores.
// ---------------------------------------------------------------------------
#define GP2 261  // pitch (uint32 words) for t2[32][GP2], 261 mod 32 = 5

__global__ __launch_bounds__(256)
void gather_h_kernel(const int* __restrict__ idx, float* __restrict__ out)
{
    __shared__ uint32_t t2[32 * GP2];      // t2[bc2][r]: half2 = (bc 2*bc2, 2*bc2+1)
    const int i0  = blockIdx.x * 256;
    const int tid = threadIdx.x;
    const int c   = tid & 3;               // 32B chunk within 128B row
    const int r0  = tid >> 2;              // 0..63

    // Prefetch all 4 indices first, then issue 4 independent row loads.
    int p[4];
#pragma unroll
    for (int it = 0; it < 4; ++it)
        p[it] = __ldg(idx + i0 + it * 64 + r0);

    uint64_t w[4][4];
#pragma unroll
    for (int it = 0; it < 4; ++it)
        ld_nc_32B(g_tin_h + (size_t)p[it] * BC_C + c * 16, w[it]);

#pragma unroll
    for (int it = 0; it < 4; ++it) {
        int r = it * 64 + r0;
#pragma unroll
        for (int k = 0; k < 4; ++k) {
            t2[(c * 8 + 2 * k + 0) * GP2 + r] = (uint32_t)(w[it][k]);
            t2[(c * 8 + 2 * k + 1) * GP2 + r] = (uint32_t)(w[it][k] >> 32);
        }
    }
    __syncthreads();

    // Write: 16 iters; 128-lane group shares bc2, consecutive r-pairs.
#pragma unroll
    for (int it = 0; it < 16; ++it) {
        int fid = it * 256 + tid;
        int bc2 = fid >> 7;                // 0..31
        int rp  = fid & 127;               // r-pair 0..127
        uint32_t a = t2[bc2 * GP2 + 2 * rp + 0];
        uint32_t b = t2[bc2 * GP2 + 2 * rp + 1];
        float2 fa = __half22float2(*reinterpret_cast<__half2*>(&a));
        float2 fb = __half22float2(*reinterpret_cast<__half2*>(&b));
        float* oL = out + (size_t)(2 * bc2 + 0) * N_OUT_C + i0 + 2 * rp;
        float* oH = out + (size_t)(2 * bc2 + 1) * N_OUT_C + i0 + 2 * rp;
        __stcs(reinterpret_cast<float2*>(oL), make_float2(fa.x, fb.x));
        __stcs(reinterpret_cast<float2*>(oH), make_float2(fa.y, fb.y));
    }
}

extern "C" void kernel_launch(void* const* d_in, const int* in_sizes, int n_in,
                              void* d_out, int out_size)
{
    const float* in_feat = (const float*)d_in[0];
    const int*   parent  = (const int*)d_in[1];
    float*       out     = (float*)d_out;

    transpose_h_kernel<<<N_IN_C / 64, 256>>>(in_feat);
    gather_h_kernel<<<N_OUT_C / 256, 256>>>(parent, out);
}

// round 9
// speedup vs baseline: 1.1489x; 1.1489x over previous
#include <cuda_runtime.h>
#include <cuda_fp16.h>
#include <cstdint>

// out[b, c, i] = in[b, c, parent_idx[i]]
// B*C = 64, N_IN = 1048576, N_OUT = 2097152, fp32.
//
// Pipeline:
//  1) transpose+convert in[64][1M] fp32 -> g_tin_h[1M][64] fp16 (128 MB).
//     One gathered row = 128B = exactly one cache line.
//  2) gather: 128 output indices per block (17 KB smem -> full 2048
//     threads/SM occupancy; SM-level MLP is what feeds random-read HBM),
//     smem transpose, coalesced fp32 float4 streaming stores.
// fp16 round-trip rel err ~2e-4 (norm), under the 1e-3 threshold.

#define N_IN_C   1048576
#define N_OUT_C  2097152
#define BC_C     64

// 128 MB scratch: transposed fp16 input, tin[n][bc]
__device__ __align__(256) __half g_tin_h[(size_t)N_IN_C * BC_C];

__device__ __forceinline__ void st_32B(void* p, const uint64_t w[4])
{
    asm volatile("st.global.v4.b64 [%0], {%1,%2,%3,%4};"
                 :: "l"(p), "l"(w[0]), "l"(w[1]), "l"(w[2]), "l"(w[3])
                 : "memory");
}

__device__ __forceinline__ void ld_nc_32B(const void* p, uint64_t w[4])
{
    asm volatile("ld.global.nc.v4.b64 {%0,%1,%2,%3}, [%4];"
                 : "=l"(w[0]), "=l"(w[1]), "=l"(w[2]), "=l"(w[3]) : "l"(p));
}

// ---------------------------------------------------------------------------
// Kernel A: transpose+convert in[64][1M] fp32 -> g_tin_h[1M][64] fp16.
// Block: 64 bc x 64 n tile, 256 threads.
// ---------------------------------------------------------------------------
__global__ __launch_bounds__(256)
void transpose_h_kernel(const float* __restrict__ in)
{
    __shared__ float t[64][65];            // [n-within-tile][bc]
    const int n0  = blockIdx.x * 64;
    const int tid = threadIdx.x;

#pragma unroll
    for (int it = 0; it < 4; ++it) {
        int fid = it * 256 + tid;
        int bc  = fid >> 4;                // 0..63
        int jc  = fid & 15;                // float4 slot
        float4 v = __ldg(reinterpret_cast<const float4*>(
                             in + (size_t)bc * N_IN_C + n0) + jc);
        t[jc * 4 + 0][bc] = v.x;
        t[jc * 4 + 1][bc] = v.y;
        t[jc * 4 + 2][bc] = v.z;
        t[jc * 4 + 3][bc] = v.w;
    }
    __syncthreads();

    // Write: each n-row = 64 halfs = 128B; thread writes one 32B chunk.
    {
        int j = tid >> 2;                  // n within tile 0..63
        int q = tid & 3;                   // 32B chunk over bc
        uint64_t w[4];
#pragma unroll
        for (int k = 0; k < 4; ++k) {
            __half2 h0 = __float22half2_rn(
                make_float2(t[j][q * 16 + k * 4 + 0], t[j][q * 16 + k * 4 + 1]));
            __half2 h1 = __float22half2_rn(
                make_float2(t[j][q * 16 + k * 4 + 2], t[j][q * 16 + k * 4 + 3]));
            uint32_t a = *reinterpret_cast<uint32_t*>(&h0);
            uint32_t b = *reinterpret_cast<uint32_t*>(&h1);
            w[k] = (uint64_t)a | ((uint64_t)b << 32);
        }
        st_32B(g_tin_h + (size_t)(n0 + j) * BC_C + q * 16, w);
    }
}

// ---------------------------------------------------------------------------
// Kernel B: gather. Block = 256 threads, 128 output indices, all 64 bc.
//  load : 4 threads per index read the 128B row as 32B v4.b64 chunks;
//         2 independent rows in flight per thread, 17 KB smem keeps full
//         thread occupancy (SM-level MLP >> per-thread MLP — R8 lesson).
//  write: 4 iters; thread handles one r-quad (4 consecutive outputs) of a
//         bc-pair -> two fully coalesced float4 streaming stores.
// ---------------------------------------------------------------------------
#define GP 133   // pitch (uint32 words) for t2[32][GP]

__global__ __launch_bounds__(256)
void gather_h_kernel(const int* __restrict__ idx, float* __restrict__ out)
{
    __shared__ uint32_t t2[32 * GP];       // t2[bc2][r]: half2 = (bc 2*bc2, 2*bc2+1)
    const int i0  = blockIdx.x * 128;
    const int tid = threadIdx.x;
    const int c   = tid & 3;               // 32B chunk within 128B row
    const int r0  = tid >> 2;              // 0..63

    // Gather: 2 independent random 128B line reads per thread.
    int p0 = __ldg(idx + i0 + r0);
    int p1 = __ldg(idx + i0 + 64 + r0);
    uint64_t w0[4], w1[4];
    ld_nc_32B(g_tin_h + (size_t)p0 * BC_C + c * 16, w0);
    ld_nc_32B(g_tin_h + (size_t)p1 * BC_C + c * 16, w1);

#pragma unroll
    for (int k = 0; k < 4; ++k) {
        t2[(c * 8 + 2 * k + 0) * GP + r0]      = (uint32_t)(w0[k]);
        t2[(c * 8 + 2 * k + 1) * GP + r0]      = (uint32_t)(w0[k] >> 32);
        t2[(c * 8 + 2 * k + 0) * GP + 64 + r0] = (uint32_t)(w1[k]);
        t2[(c * 8 + 2 * k + 1) * GP + 64 + r0] = (uint32_t)(w1[k] >> 32);
    }
    __syncthreads();

    // Write: 4 iters; fid -> (bc2 0..31, rq 0..31); thread converts a
    // 4-wide run of outputs for both channels of its bc-pair.
#pragma unroll
    for (int it = 0; it < 4; ++it) {
        int fid = it * 256 + tid;
        int bc2 = fid >> 5;                // 0..31
        int rq  = fid & 31;                // r-quad 0..31 (4 outputs each)
        const uint32_t* row = &t2[bc2 * GP + rq * 4];
        float2 f0 = __half22float2(*reinterpret_cast<const __half2*>(&row[0]));
        float2 f1 = __half22float2(*reinterpret_cast<const __half2*>(&row[1]));
        float2 f2 = __half22float2(*reinterpret_cast<const __half2*>(&row[2]));
        float2 f3 = __half22float2(*reinterpret_cast<const __half2*>(&row[3]));
        float* oL = out + (size_t)(2 * bc2 + 0) * N_OUT_C + i0 + rq * 4;
        float* oH = out + (size_t)(2 * bc2 + 1) * N_OUT_C + i0 + rq * 4;
        __stcs(reinterpret_cast<float4*>(oL), make_float4(f0.x, f1.x, f2.x, f3.x));
        __stcs(reinterpret_cast<float4*>(oH), make_float4(f0.y, f1.y, f2.y, f3.y));
    }
}

extern "C" void kernel_launch(void* const* d_in, const int* in_sizes, int n_in,
                              void* d_out, int out_size)
{
    const float* in_feat = (const float*)d_in[0];
    const int*   parent  = (const int*)d_in[1];
    float*       out     = (float*)d_out;

    transpose_h_kernel<<<N_IN_C / 64, 256>>>(in_feat);
    gather_h_kernel<<<N_OUT_C / 128, 256>>>(parent, out);
}

// round 10
// speedup vs baseline: 1.1670x; 1.0158x over previous
#include <cuda_runtime.h>
#include <cuda_fp16.h>
#include <cstdint>

// out[b, c, i] = in[b, c, parent_idx[i]]
// B*C = 64, N_IN = 1048576, N_OUT = 2097152, fp32.
//
// Converged architecture (R6 config — empirical argmax):
//  1) transpose+convert in[64][1M] fp32 -> g_tin_h[1M][64] fp16 (128 MB).
//     One gathered row = 128B = exactly one L2 line.
//  2) gather: 128 output indices per block (17 KB smem -> full thread
//     occupancy), 2 independent random 128B row loads per thread, smem
//     transpose, coalesced fp32 float2 streaming stores.
// Measured: ~1.07 GB total DRAM traffic, within ~1.5% of the access-mix
// bandwidth floor. fp16 round-trip rel err ~2e-4, under the 1e-3 threshold.

#define N_IN_C   1048576
#define N_OUT_C  2097152
#define BC_C     64

// 128 MB scratch: transposed fp16 input, tin[n][bc]
__device__ __align__(256) __half g_tin_h[(size_t)N_IN_C * BC_C];

__device__ __forceinline__ void st_evict_last_32B(void* p, const uint64_t w[4])
{
    asm volatile("st.global.L2::evict_last.v4.b64 [%0], {%1,%2,%3,%4};"
                 :: "l"(p), "l"(w[0]), "l"(w[1]), "l"(w[2]), "l"(w[3])
                 : "memory");
}

__device__ __forceinline__ void ld_nc_evict_last_32B(const void* p, uint64_t w[4])
{
    asm volatile("ld.global.nc.L2::evict_last.v4.b64 {%0,%1,%2,%3}, [%4];"
                 : "=l"(w[0]), "=l"(w[1]), "=l"(w[2]), "=l"(w[3]) : "l"(p));
}

// ---------------------------------------------------------------------------
// Kernel A: transpose+convert in[64][1M] fp32 -> g_tin_h[1M][64] fp16.
// Block: 64 bc x 64 n tile, 256 threads.
// ---------------------------------------------------------------------------
__global__ __launch_bounds__(256)
void transpose_h_kernel(const float* __restrict__ in)
{
    __shared__ float t[64][65];            // [n-within-tile][bc]
    const int n0  = blockIdx.x * 64;
    const int tid = threadIdx.x;

    // Load: coalesced float4 rows per bc
#pragma unroll
    for (int it = 0; it < 4; ++it) {
        int fid = it * 256 + tid;
        int bc  = fid >> 4;                // 0..63
        int jc  = fid & 15;                // float4 slot
        float4 v = __ldg(reinterpret_cast<const float4*>(
                             in + (size_t)bc * N_IN_C + n0) + jc);
        t[jc * 4 + 0][bc] = v.x;
        t[jc * 4 + 1][bc] = v.y;
        t[jc * 4 + 2][bc] = v.z;
        t[jc * 4 + 3][bc] = v.w;
    }
    __syncthreads();

    // Write: each n-row = 64 halfs = 128B; thread writes one 32B chunk
    // (16 halfs = bc q*16..q*16+15).
    {
        int j = tid >> 2;                  // n within tile 0..63
        int q = tid & 3;                   // 32B chunk over bc
        uint64_t w[4];
#pragma unroll
        for (int k = 0; k < 4; ++k) {
            __half2 h0 = __float22half2_rn(
                make_float2(t[j][q * 16 + k * 4 + 0], t[j][q * 16 + k * 4 + 1]));
            __half2 h1 = __float22half2_rn(
                make_float2(t[j][q * 16 + k * 4 + 2], t[j][q * 16 + k * 4 + 3]));
            uint32_t a = *reinterpret_cast<uint32_t*>(&h0);
            uint32_t b = *reinterpret_cast<uint32_t*>(&h1);
            w[k] = (uint64_t)a | ((uint64_t)b << 32);
        }
        st_evict_last_32B(g_tin_h + (size_t)(n0 + j) * BC_C + q * 16, w);
    }
}

// ---------------------------------------------------------------------------
// Kernel B: gather. Block = 256 threads, 128 output indices, all 64 bc.
//  load : 4 threads per index read the 128B row as 32B v4.b64 chunks;
//         2 independent rows in flight per thread; 17 KB smem keeps full
//         thread occupancy (SM-level outstanding-load count is the lever).
//  write: thread reads rows 2rp, 2rp+1 of one bc-pair -> two float2 stores,
//         fully coalesced over consecutive i; __stcs streaming.
// ---------------------------------------------------------------------------
#define GP 133   // pitch (uint32 words) for t2[32][GP]

__global__ __launch_bounds__(256)
void gather_h_kernel(const int* __restrict__ idx, float* __restrict__ out)
{
    __shared__ uint32_t t2[32 * GP];       // t2[bc2][r]: half2 = (bc 2*bc2, 2*bc2+1)
    const int i0  = blockIdx.x * 128;
    const int tid = threadIdx.x;
    const int c   = tid & 3;               // 32B chunk within 128B row
    const int r0  = tid >> 2;              // 0..63

    // Gather: 2 iters x 64 rows; one random 128B line per index.
#pragma unroll
    for (int it = 0; it < 2; ++it) {
        int r = it * 64 + r0;
        int p = __ldg(idx + i0 + r);       // broadcast within 4-lane group
        uint64_t w[4];
        ld_nc_evict_last_32B(g_tin_h + (size_t)p * BC_C + c * 16, w);
#pragma unroll
        for (int k = 0; k < 4; ++k) {
            t2[(c * 8 + 2 * k + 0) * GP + r] = (uint32_t)(w[k]);
            t2[(c * 8 + 2 * k + 1) * GP + r] = (uint32_t)(w[k] >> 32);
        }
    }
    __syncthreads();

    // Write: 8 iters; 64-lane group shares bc2, consecutive r-pairs;
    // streaming stores so the 512MB output doesn't churn L2.
#pragma unroll
    for (int it = 0; it < 8; ++it) {
        int fid = it * 256 + tid;
        int bc2 = fid >> 6;                // 0..31
        int rp  = fid & 63;                // r-pair 0..63
        uint32_t a = t2[bc2 * GP + 2 * rp + 0];
        uint32_t b = t2[bc2 * GP + 2 * rp + 1];
        float2 fa = __half22float2(*reinterpret_cast<__half2*>(&a));
        float2 fb = __half22float2(*reinterpret_cast<__half2*>(&b));
        float* oL = out + (size_t)(2 * bc2 + 0) * N_OUT_C + i0 + 2 * rp;
        float* oH = out + (size_t)(2 * bc2 + 1) * N_OUT_C + i0 + 2 * rp;
        float2 vL = make_float2(fa.x, fb.x);
        float2 vH = make_float2(fa.y, fb.y);
        __stcs(reinterpret_cast<float2*>(oL), vL);
        __stcs(reinterpret_cast<float2*>(oH), vH);
    }
}

extern "C" void kernel_launch(void* const* d_in, const int* in_sizes, int n_in,
                              void* d_out, int out_size)
{
    const float* in_feat = (const float*)d_in[0];
    const int*   parent  = (const int*)d_in[1];
    float*       out     = (float*)d_out;

    transpose_h_kernel<<<N_IN_C / 64, 256>>>(in_feat);
    gather_h_kernel<<<N_OUT_C / 128, 256>>>(parent, out);
}